// round 1
// baseline (speedup 1.0000x reference)
#include <cuda_runtime.h>
#include <cstdint>
#include <cstddef>

#define BB 64
#define SS 512
#define DD 512
#define HH 512
#define GG 2048   // 4*HH

#define NBLK 128  // recurrent grid (must be <= resident SM count)

// ---------------- scratch (static device globals; no runtime allocation) ----
__device__ float g_xg[(size_t)BB * SS * GG];   // [B,S,4H] precomputed input gates (256 MiB)
__device__ unsigned int g_cnt[SS];             // per-step arrival counters

// ---------------- kernel 0: zero the step counters ---------------------------
__global__ void zero_cnt_kernel() {
    g_cnt[threadIdx.x] = 0u;
}

// ---------------- kernel 1: xg = inputs @ W_ih^T + (b_ih + b_hh) -------------
// inputs[b,s,:] = emb[b,:] if s==0 else x[b,s-1,:]
// Classic 128x128x8 fp32 SGEMM, 256 threads, 8x8 per thread.
__global__ __launch_bounds__(256) void xg_gemm_kernel(
    const float* __restrict__ x, const float* __restrict__ emb,
    const float* __restrict__ W_ih, const float* __restrict__ b_ih,
    const float* __restrict__ b_hh)
{
    __shared__ float As[8][132];
    __shared__ float Bsh[8][132];

    const int tid = threadIdx.x;
    const int tx = tid & 15;        // n-tile position
    const int ty = tid >> 4;        // m-tile position
    const int mBase = blockIdx.y * 128;
    const int nBase = blockIdx.x * 128;

    float acc[8][8];
    #pragma unroll
    for (int i = 0; i < 8; i++)
        #pragma unroll
        for (int j = 0; j < 8; j++) acc[i][j] = 0.f;

    // loader mapping: 256 threads -> 128 rows x 2 float4
    const int lrow = tid >> 1;
    const int lkp  = (tid & 1) * 4;

    // A row source pointer (constant across k tiles)
    const int m    = mBase + lrow;
    const int bidx = m >> 9;        // / SS
    const int sidx = m & 511;       // % SS
    const float* aSrc = (sidx == 0) ? (emb + (size_t)bidx * DD)
                                    : (x + ((size_t)bidx * SS + (sidx - 1)) * DD);
    const float* bSrc = W_ih + (size_t)(nBase + lrow) * DD;

    for (int k0 = 0; k0 < DD; k0 += 8) {
        float4 av = *(const float4*)(aSrc + k0 + lkp);
        float4 bv = *(const float4*)(bSrc + k0 + lkp);
        As[lkp + 0][lrow] = av.x;
        As[lkp + 1][lrow] = av.y;
        As[lkp + 2][lrow] = av.z;
        As[lkp + 3][lrow] = av.w;
        Bsh[lkp + 0][lrow] = bv.x;
        Bsh[lkp + 1][lrow] = bv.y;
        Bsh[lkp + 2][lrow] = bv.z;
        Bsh[lkp + 3][lrow] = bv.w;
        __syncthreads();

        #pragma unroll
        for (int kk = 0; kk < 8; kk++) {
            float ar[8], br[8];
            *(float4*)&ar[0] = *(const float4*)&As[kk][ty * 8];
            *(float4*)&ar[4] = *(const float4*)&As[kk][ty * 8 + 4];
            *(float4*)&br[0] = *(const float4*)&Bsh[kk][tx * 8];
            *(float4*)&br[4] = *(const float4*)&Bsh[kk][tx * 8 + 4];
            #pragma unroll
            for (int i = 0; i < 8; i++)
                #pragma unroll
                for (int j = 0; j < 8; j++)
                    acc[i][j] += ar[i] * br[j];
        }
        __syncthreads();
    }

    // epilogue: add bias, store
    float bias[8];
    #pragma unroll
    for (int j = 0; j < 8; j++) {
        int n = nBase + tx * 8 + j;
        bias[j] = b_ih[n] + b_hh[n];
    }
    #pragma unroll
    for (int i = 0; i < 8; i++) {
        size_t row = (size_t)(mBase + ty * 8 + i) * GG + nBase + tx * 8;
        float4 v0, v1;
        v0.x = acc[i][0] + bias[0]; v0.y = acc[i][1] + bias[1];
        v0.z = acc[i][2] + bias[2]; v0.w = acc[i][3] + bias[3];
        v1.x = acc[i][4] + bias[4]; v1.y = acc[i][5] + bias[5];
        v1.z = acc[i][6] + bias[6]; v1.w = acc[i][7] + bias[7];
        *(float4*)(g_xg + row)     = v0;
        *(float4*)(g_xg + row + 4) = v1;
    }
}

// ---------------- kernel 2: persistent LSTM recurrence -----------------------
// 128 blocks = 32 hidden-groups (16 units) x 4 batch-groups (16 batches).
// Each block: W_hh slice (64 rows x 512) resident in shared for all steps.
// Per step: gates = h_{t-1} @ Wslice^T (K-split over 8 slices, reduce in smem),
// then elementwise LSTM; h_t written to out[:, t, :]; grid barrier via g_cnt.
#define W_STRIDE 516   // 512 + 4 pad (bank-conflict avoidance)
#define RED_RSTR 17    // reduce buffer row stride

__global__ __launch_bounds__(256) void lstm_rec_kernel(
    const float* __restrict__ h_n, const float* __restrict__ c_n,
    const float* __restrict__ W_hh, float* __restrict__ out)
{
    extern __shared__ float sm[];
    float* Ws  = sm;                               // 64 x 516
    float* hs  = sm + 64 * W_STRIDE;               // 16 x 516
    float* red = sm + 64 * W_STRIDE + 16 * W_STRIDE; // 8 x (64*17) = 8704

    const int tid = threadIdx.x;
    const int hg = blockIdx.x & 31;   // hidden group
    const int bg = blockIdx.x >> 5;   // batch group
    const int j0 = hg * 16;
    const int b0 = bg * 16;

    // Load W_hh slice once: local row r -> gate = r>>4, jj = r&15
    for (int idx = tid; idx < 64 * 128; idx += 256) {
        int r  = idx >> 7;
        int kq = (idx & 127) * 4;
        int gate = r >> 4, jj = r & 15;
        float4 v = *(const float4*)(W_hh + (size_t)(gate * HH + j0 + jj) * HH + kq);
        *(float4*)(Ws + r * W_STRIDE + kq) = v;
    }

    // GEMM decomposition: 8 k-slices x (8 row-groups x 4 col-groups)
    const int ksl = tid >> 5;       // 0..7 : k slice (64 k each)
    const int sp  = tid & 31;
    const int sr  = sp >> 2;        // 0..7 : rows r = sr + 8*i
    const int sc  = sp & 3;         // 0..3 : cols b = sc*4 + j
    const int kbase = ksl * 64;

    // activation mapping: thread -> (hidden jj_a, batch bb_a)
    const int jj_a = tid & 15;
    const int bb_a = tid >> 4;
    float creg = 0.f;

    #pragma unroll 1
    for (int t = 0; t < SS; t++) {
        if (t > 0) {
            if (tid == 0) {
                while (atomicAdd(&g_cnt[t - 1], 0u) < (unsigned)NBLK) { }
                __threadfence();
            }
            __syncthreads();
        }

        // load h_{t-1} for our 16 batches into shared (L1-bypassing for out)
        for (int idx = tid; idx < 16 * 128; idx += 256) {
            int bb = idx >> 7;
            int kq = (idx & 127) * 4;
            float4 v;
            if (t == 0)
                v = *(const float4*)(h_n + (size_t)(b0 + bb) * HH + kq);
            else
                v = __ldcg((const float4*)(out + ((size_t)(b0 + bb) * SS + (t - 1)) * HH + kq));
            *(float4*)(hs + bb * W_STRIDE + kq) = v;
        }

        // issue xg loads early (held in regs through the GEMM)
        size_t xb = ((size_t)(b0 + bb_a) * SS + t) * GG + j0 + jj_a;
        float xg0 = g_xg[xb];
        float xg1 = g_xg[xb + HH];
        float xg2 = g_xg[xb + 2 * HH];
        float xg3 = g_xg[xb + 3 * HH];
        __syncthreads();

        // partial GEMM over this thread's k slice
        float acc[8][4];
        #pragma unroll
        for (int i = 0; i < 8; i++)
            #pragma unroll
            for (int j = 0; j < 4; j++) acc[i][j] = 0.f;

        #pragma unroll 4
        for (int k = 0; k < 64; k += 4) {
            float4 hv0 = *(const float4*)(hs + (sc * 4 + 0) * W_STRIDE + kbase + k);
            float4 hv1 = *(const float4*)(hs + (sc * 4 + 1) * W_STRIDE + kbase + k);
            float4 hv2 = *(const float4*)(hs + (sc * 4 + 2) * W_STRIDE + kbase + k);
            float4 hv3 = *(const float4*)(hs + (sc * 4 + 3) * W_STRIDE + kbase + k);
            #pragma unroll
            for (int i = 0; i < 8; i++) {
                float4 wv = *(const float4*)(Ws + (sr + 8 * i) * W_STRIDE + kbase + k);
                acc[i][0] += wv.x * hv0.x + wv.y * hv0.y + wv.z * hv0.z + wv.w * hv0.w;
                acc[i][1] += wv.x * hv1.x + wv.y * hv1.y + wv.z * hv1.z + wv.w * hv1.w;
                acc[i][2] += wv.x * hv2.x + wv.y * hv2.y + wv.z * hv2.z + wv.w * hv2.w;
                acc[i][3] += wv.x * hv3.x + wv.y * hv3.y + wv.z * hv3.z + wv.w * hv3.w;
            }
        }

        // write partials for cross-slice reduction
        #pragma unroll
        for (int i = 0; i < 8; i++) {
            int r = sr + 8 * i;
            float* rp = red + ksl * 1088 + r * RED_RSTR + sc * 4;
            rp[0] = acc[i][0]; rp[1] = acc[i][1]; rp[2] = acc[i][2]; rp[3] = acc[i][3];
        }
        __syncthreads();

        // reduce 8 slices + LSTM elementwise for (jj_a, bb_a)
        float s0 = 0.f, s1 = 0.f, s2 = 0.f, s3 = 0.f;
        #pragma unroll
        for (int ks2 = 0; ks2 < 8; ks2++) {
            const float* rp = red + ks2 * 1088;
            s0 += rp[(0 * 16 + jj_a) * RED_RSTR + bb_a];
            s1 += rp[(1 * 16 + jj_a) * RED_RSTR + bb_a];
            s2 += rp[(2 * 16 + jj_a) * RED_RSTR + bb_a];
            s3 += rp[(3 * 16 + jj_a) * RED_RSTR + bb_a];
        }
        float ig = 1.f / (1.f + __expf(-(xg0 + s0)));
        float fg = 1.f / (1.f + __expf(-(xg1 + s1)));
        float gc = tanhf(xg2 + s2);
        float og = 1.f / (1.f + __expf(-(xg3 + s3)));
        if (t == 0) creg = c_n[(size_t)(b0 + bb_a) * HH + j0 + jj_a];
        creg = fg * creg + ig * gc;
        float hval = og * tanhf(creg);
        out[((size_t)(b0 + bb_a) * SS + t) * HH + j0 + jj_a] = hval;

        __syncthreads();
        if (tid == 0) {
            __threadfence();
            atomicAdd(&g_cnt[t], 1u);
        }
    }
}

// ---------------- launch ------------------------------------------------------
extern "C" void kernel_launch(void* const* d_in, const int* in_sizes, int n_in,
                              void* d_out, int out_size)
{
    const float* x    = (const float*)d_in[0];   // [B,S,D]
    const float* emb  = (const float*)d_in[1];   // [B,D]
    const float* h_n  = (const float*)d_in[2];   // [1,B,H]
    const float* c_n  = (const float*)d_in[3];   // [1,B,H]
    const float* W_ih = (const float*)d_in[4];   // [4H,D]
    const float* W_hh = (const float*)d_in[5];   // [4H,H]
    const float* b_ih = (const float*)d_in[6];   // [4H]
    const float* b_hh = (const float*)d_in[7];   // [4H]
    float* out = (float*)d_out;                  // [B,S,H]

    const int smemRec = (64 * W_STRIDE + 16 * W_STRIDE + 8 * 1088) * (int)sizeof(float); // 199936 B
    cudaFuncSetAttribute(lstm_rec_kernel, cudaFuncAttributeMaxDynamicSharedMemorySize, smemRec);

    zero_cnt_kernel<<<1, SS>>>();
    xg_gemm_kernel<<<dim3(GG / 128, (BB * SS) / 128), 256>>>(x, emb, W_ih, b_ih, b_hh);
    lstm_rec_kernel<<<NBLK, 256, smemRec>>>(h_n, c_n, W_hh, out);
}

// round 3
// speedup vs baseline: 1.2846x; 1.2846x over previous
#include <cuda_runtime.h>
#include <cstdint>
#include <cstddef>

#define BB 64
#define SS 512
#define DD 512
#define HH 512
#define GG 2048   // 4*HH

#define NBLK 128  // recurrent grid (32 hidden-groups x 4 batch-groups)

// ---------------- scratch ----------------------------------------------------
__device__ float g_xg[(size_t)BB * SS * GG];   // [B,S,4H] precomputed input gates
__device__ unsigned int g_cnt[4 * SS];         // per-(batchgroup,step) arrival counters

__global__ void zero_cnt_kernel() {
    int i = blockIdx.x * blockDim.x + threadIdx.x;
    if (i < 4 * SS) g_cnt[i] = 0u;
}

// ---------------- helpers -----------------------------------------------------
__device__ __forceinline__ uint32_t to_tf32(float f) {
    uint32_t u;
    asm("cvt.rna.tf32.f32 %0, %1;" : "=r"(u) : "f"(f));
    return u;
}

__device__ __forceinline__ void mma_tf32(float& c0, float& c1, float& c2, float& c3,
                                         uint32_t a0, uint32_t a1, uint32_t a2, uint32_t a3,
                                         uint32_t b0, uint32_t b1) {
    asm volatile(
        "mma.sync.aligned.m16n8k8.row.col.f32.tf32.tf32.f32 "
        "{%0,%1,%2,%3}, {%4,%5,%6,%7}, {%8,%9}, {%0,%1,%2,%3};"
        : "+f"(c0), "+f"(c1), "+f"(c2), "+f"(c3)
        : "r"(a0), "r"(a1), "r"(a2), "r"(a3), "r"(b0), "r"(b1));
}

// ---------------- kernel 1: xg = inputs @ W_ih^T + bias via mma.sync tf32 ----
// Block tile 128(M) x 128(N), K staged 32 at a time. 256 threads = 8 warps,
// warp grid 2(m) x 4(n), warp tile 64 x 32, mma m16n8k8 (4 mfrag x 4 nfrag).
#define KC 32
#define ASTR 36   // smem row stride in floats (128B-friendly, conflict-spreading)

__global__ __launch_bounds__(256) void xg_mma_kernel(
    const float* __restrict__ x, const float* __restrict__ emb,
    const float* __restrict__ W_ih, const float* __restrict__ b_ih,
    const float* __restrict__ b_hh)
{
    __shared__ uint32_t As[128 * ASTR];
    __shared__ uint32_t Bs[128 * ASTR];

    const int tid  = threadIdx.x;
    const int wid  = tid >> 5;
    const int lane = tid & 31;
    const int nBase = blockIdx.x * 128;
    const int mBase = blockIdx.y * 128;

    // -------- loader mapping: 1024 float4-slots, 4 per thread ---------------
    // slot = tid + i*256 ; row = slot>>3 ; q = slot&7  (col q*4..q*4+3)
    const float* aSrc[4];
    const float* bSrc[4];
    int lRow[4], lQ[4];
    #pragma unroll
    for (int i = 0; i < 4; i++) {
        int slot = tid + i * 256;
        int r = slot >> 3;
        lRow[i] = r;
        lQ[i] = slot & 7;
        int m = mBase + r;
        int bidx = m >> 9, sidx = m & 511;
        aSrc[i] = (sidx == 0) ? (emb + (size_t)bidx * DD)
                              : (x + ((size_t)bidx * SS + (sidx - 1)) * DD);
        bSrc[i] = W_ih + (size_t)(nBase + r) * DD;
    }

    // -------- accumulators ---------------------------------------------------
    float acc[4][4][4];   // [mfrag][nfrag][reg]
    #pragma unroll
    for (int mf = 0; mf < 4; mf++)
        #pragma unroll
        for (int nf = 0; nf < 4; nf++)
            #pragma unroll
            for (int r = 0; r < 4; r++) acc[mf][nf][r] = 0.f;

    const int wm = (wid >> 2) * 64;
    const int wn = (wid & 3) * 32;
    const int lg = lane >> 2;   // group id 0..7
    const int lt = lane & 3;    // id in group 0..3

    // -------- prefetch chunk 0 ----------------------------------------------
    float4 pfA[4], pfB[4];
    #pragma unroll
    for (int i = 0; i < 4; i++) {
        pfA[i] = *(const float4*)(aSrc[i] + lQ[i] * 4);
        pfB[i] = *(const float4*)(bSrc[i] + lQ[i] * 4);
    }

    #pragma unroll 1
    for (int c = 0; c < DD / KC; c++) {
        // store prefetched chunk (tf32-rounded)
        #pragma unroll
        for (int i = 0; i < 4; i++) {
            uint32_t* pa = &As[lRow[i] * ASTR + lQ[i] * 4];
            uint32_t* pb = &Bs[lRow[i] * ASTR + lQ[i] * 4];
            pa[0] = to_tf32(pfA[i].x); pa[1] = to_tf32(pfA[i].y);
            pa[2] = to_tf32(pfA[i].z); pa[3] = to_tf32(pfA[i].w);
            pb[0] = to_tf32(pfB[i].x); pb[1] = to_tf32(pfB[i].y);
            pb[2] = to_tf32(pfB[i].z); pb[3] = to_tf32(pfB[i].w);
        }
        __syncthreads();

        // prefetch next chunk
        if (c + 1 < DD / KC) {
            int ksrc = (c + 1) * KC;
            #pragma unroll
            for (int i = 0; i < 4; i++) {
                pfA[i] = *(const float4*)(aSrc[i] + ksrc + lQ[i] * 4);
                pfB[i] = *(const float4*)(bSrc[i] + ksrc + lQ[i] * 4);
            }
        }

        // compute on smem chunk: 4 k-steps of 8
        #pragma unroll
        for (int kk = 0; kk < KC; kk += 8) {
            uint32_t a[4][4];
            #pragma unroll
            for (int mf = 0; mf < 4; mf++) {
                int r = wm + mf * 16 + lg;
                a[mf][0] = As[r * ASTR + kk + lt];
                a[mf][1] = As[(r + 8) * ASTR + kk + lt];
                a[mf][2] = As[r * ASTR + kk + lt + 4];
                a[mf][3] = As[(r + 8) * ASTR + kk + lt + 4];
            }
            uint32_t b[4][2];
            #pragma unroll
            for (int nf = 0; nf < 4; nf++) {
                int n = wn + nf * 8 + lg;
                b[nf][0] = Bs[n * ASTR + kk + lt];
                b[nf][1] = Bs[n * ASTR + kk + lt + 4];
            }
            #pragma unroll
            for (int mf = 0; mf < 4; mf++)
                #pragma unroll
                for (int nf = 0; nf < 4; nf++)
                    mma_tf32(acc[mf][nf][0], acc[mf][nf][1], acc[mf][nf][2], acc[mf][nf][3],
                             a[mf][0], a[mf][1], a[mf][2], a[mf][3],
                             b[nf][0], b[nf][1]);
        }
        __syncthreads();
    }

    // -------- epilogue: bias add + store ------------------------------------
    #pragma unroll
    for (int nf = 0; nf < 4; nf++) {
        int n0 = nBase + wn + nf * 8 + 2 * lt;
        float bias0 = b_ih[n0] + b_hh[n0];
        float bias1 = b_ih[n0 + 1] + b_hh[n0 + 1];
        #pragma unroll
        for (int mf = 0; mf < 4; mf++) {
            int m0 = mBase + wm + mf * 16 + lg;
            float2 v0, v1;
            v0.x = acc[mf][nf][0] + bias0;
            v0.y = acc[mf][nf][1] + bias1;
            v1.x = acc[mf][nf][2] + bias0;
            v1.y = acc[mf][nf][3] + bias1;
            *(float2*)(g_xg + (size_t)m0 * GG + n0) = v0;
            *(float2*)(g_xg + (size_t)(m0 + 8) * GG + n0) = v1;
        }
    }
}

// ---------------- kernel 2: persistent LSTM recurrence -----------------------
#define W_STRIDE 516
#define RED_RSTR 17

__global__ __launch_bounds__(256) void lstm_rec_kernel(
    const float* __restrict__ h_n, const float* __restrict__ c_n,
    const float* __restrict__ W_hh, float* __restrict__ out)
{
    extern __shared__ float sm[];
    float* Ws  = sm;                                  // 64 x 516
    float* hs  = sm + 64 * W_STRIDE;                  // 16 x 516
    float* red = sm + 64 * W_STRIDE + 16 * W_STRIDE;  // 8 x 1088

    const int tid = threadIdx.x;
    const int hg = blockIdx.x & 31;
    const int bg = blockIdx.x >> 5;
    const int j0 = hg * 16;
    const int b0 = bg * 16;

    for (int idx = tid; idx < 64 * 128; idx += 256) {
        int r  = idx >> 7;
        int kq = (idx & 127) * 4;
        int gate = r >> 4, jj = r & 15;
        float4 v = *(const float4*)(W_hh + (size_t)(gate * HH + j0 + jj) * HH + kq);
        *(float4*)(Ws + r * W_STRIDE + kq) = v;
    }

    const int ksl = tid >> 5;
    const int sp  = tid & 31;
    const int sr  = sp >> 2;
    const int sc  = sp & 3;
    const int kbase = ksl * 64;

    const int jj_a = tid & 15;
    const int bb_a = tid >> 4;
    float creg = 0.f;

    #pragma unroll 1
    for (int t = 0; t < SS; t++) {
        if (t > 0) {
            if (tid == 0) {
                volatile unsigned int* p = &g_cnt[bg * SS + (t - 1)];
                while (*p < 32u) { }
                __threadfence();
            }
            __syncthreads();
        }

        for (int idx = tid; idx < 16 * 128; idx += 256) {
            int bb = idx >> 7;
            int kq = (idx & 127) * 4;
            float4 v;
            if (t == 0)
                v = *(const float4*)(h_n + (size_t)(b0 + bb) * HH + kq);
            else
                v = __ldcg((const float4*)(out + ((size_t)(b0 + bb) * SS + (t - 1)) * HH + kq));
            *(float4*)(hs + bb * W_STRIDE + kq) = v;
        }

        size_t xb = ((size_t)(b0 + bb_a) * SS + t) * GG + j0 + jj_a;
        float xg0 = g_xg[xb];
        float xg1 = g_xg[xb + HH];
        float xg2 = g_xg[xb + 2 * HH];
        float xg3 = g_xg[xb + 3 * HH];
        __syncthreads();

        float acc[8][4];
        #pragma unroll
        for (int i = 0; i < 8; i++)
            #pragma unroll
            for (int j = 0; j < 4; j++) acc[i][j] = 0.f;

        #pragma unroll 4
        for (int k = 0; k < 64; k += 4) {
            float4 hv0 = *(const float4*)(hs + (sc * 4 + 0) * W_STRIDE + kbase + k);
            float4 hv1 = *(const float4*)(hs + (sc * 4 + 1) * W_STRIDE + kbase + k);
            float4 hv2 = *(const float4*)(hs + (sc * 4 + 2) * W_STRIDE + kbase + k);
            float4 hv3 = *(const float4*)(hs + (sc * 4 + 3) * W_STRIDE + kbase + k);
            #pragma unroll
            for (int i = 0; i < 8; i++) {
                float4 wv = *(const float4*)(Ws + (sr + 8 * i) * W_STRIDE + kbase + k);
                acc[i][0] += wv.x * hv0.x + wv.y * hv0.y + wv.z * hv0.z + wv.w * hv0.w;
                acc[i][1] += wv.x * hv1.x + wv.y * hv1.y + wv.z * hv1.z + wv.w * hv1.w;
                acc[i][2] += wv.x * hv2.x + wv.y * hv2.y + wv.z * hv2.z + wv.w * hv2.w;
                acc[i][3] += wv.x * hv3.x + wv.y * hv3.y + wv.z * hv3.z + wv.w * hv3.w;
            }
        }

        #pragma unroll
        for (int i = 0; i < 8; i++) {
            int r = sr + 8 * i;
            float* rp = red + ksl * 1088 + r * RED_RSTR + sc * 4;
            rp[0] = acc[i][0]; rp[1] = acc[i][1]; rp[2] = acc[i][2]; rp[3] = acc[i][3];
        }
        __syncthreads();

        float s0 = 0.f, s1 = 0.f, s2 = 0.f, s3 = 0.f;
        #pragma unroll
        for (int ks2 = 0; ks2 < 8; ks2++) {
            const float* rp = red + ks2 * 1088;
            s0 += rp[(0 * 16 + jj_a) * RED_RSTR + bb_a];
            s1 += rp[(1 * 16 + jj_a) * RED_RSTR + bb_a];
            s2 += rp[(2 * 16 + jj_a) * RED_RSTR + bb_a];
            s3 += rp[(3 * 16 + jj_a) * RED_RSTR + bb_a];
        }
        float ig = 1.f / (1.f + __expf(-(xg0 + s0)));
        float fg = 1.f / (1.f + __expf(-(xg1 + s1)));
        float gc = tanhf(xg2 + s2);
        float og = 1.f / (1.f + __expf(-(xg3 + s3)));
        if (t == 0) creg = c_n[(size_t)(b0 + bb_a) * HH + j0 + jj_a];
        creg = fg * creg + ig * gc;
        float hval = og * tanhf(creg);
        out[((size_t)(b0 + bb_a) * SS + t) * HH + j0 + jj_a] = hval;

        __syncthreads();
        if (tid == 0) {
            __threadfence();
            atomicAdd(&g_cnt[bg * SS + t], 1u);
        }
    }
}

// ---------------- launch ------------------------------------------------------
extern "C" void kernel_launch(void* const* d_in, const int* in_sizes, int n_in,
                              void* d_out, int out_size)
{
    const float* x    = (const float*)d_in[0];
    const float* emb  = (const float*)d_in[1];
    const float* h_n  = (const float*)d_in[2];
    const float* c_n  = (const float*)d_in[3];
    const float* W_ih = (const float*)d_in[4];
    const float* W_hh = (const float*)d_in[5];
    const float* b_ih = (const float*)d_in[6];
    const float* b_hh = (const float*)d_in[7];
    float* out = (float*)d_out;

    const int smemRec = (64 * W_STRIDE + 16 * W_STRIDE + 8 * 1088) * (int)sizeof(float);
    cudaFuncSetAttribute(lstm_rec_kernel, cudaFuncAttributeMaxDynamicSharedMemorySize, smemRec);

    zero_cnt_kernel<<<2, 1024>>>();
    xg_mma_kernel<<<dim3(GG / 128, (BB * SS) / 128), 256>>>(x, emb, W_ih, b_ih, b_hh);
    lstm_rec_kernel<<<NBLK, 256, smemRec>>>(h_n, c_n, W_hh, out);
}

// round 5
// speedup vs baseline: 2.3540x; 1.8325x over previous
#include <cuda_runtime.h>
#include <cstdint>
#include <cstddef>

#define BB 64
#define SS 512
#define DD 512
#define HH 512
#define GG 2048   // 4*HH

#define NBLK 128  // recurrent grid (32 hidden-groups x 4 batch-groups)

// ---------------- scratch ----------------------------------------------------
__device__ float g_xg[(size_t)BB * SS * GG];   // [B,S,4H] precomputed input gates
__device__ unsigned int g_cnt[4 * SS];         // per-(batchgroup,step) arrival counters

__global__ void zero_cnt_kernel() {
    int i = blockIdx.x * blockDim.x + threadIdx.x;
    if (i < 4 * SS) g_cnt[i] = 0u;
}

// ---------------- helpers -----------------------------------------------------
__device__ __forceinline__ uint32_t to_tf32(float f) {
    uint32_t u;
    asm("cvt.rna.tf32.f32 %0, %1;" : "=r"(u) : "f"(f));
    return u;
}

__device__ __forceinline__ void mma_tf32(float& c0, float& c1, float& c2, float& c3,
                                         uint32_t a0, uint32_t a1, uint32_t a2, uint32_t a3,
                                         uint32_t b0, uint32_t b1) {
    asm volatile(
        "mma.sync.aligned.m16n8k8.row.col.f32.tf32.tf32.f32 "
        "{%0,%1,%2,%3}, {%4,%5,%6,%7}, {%8,%9}, {%0,%1,%2,%3};"
        : "+f"(c0), "+f"(c1), "+f"(c2), "+f"(c3)
        : "r"(a0), "r"(a1), "r"(a2), "r"(a3), "r"(b0), "r"(b1));
}

// ---------------- kernel 1: xg = inputs @ W_ih^T + bias via mma.sync tf32 ----
#define KC 32
#define ASTR 36

__global__ __launch_bounds__(256) void xg_mma_kernel(
    const float* __restrict__ x, const float* __restrict__ emb,
    const float* __restrict__ W_ih, const float* __restrict__ b_ih,
    const float* __restrict__ b_hh)
{
    __shared__ uint32_t As[128 * ASTR];
    __shared__ uint32_t Bs[128 * ASTR];

    const int tid  = threadIdx.x;
    const int wid  = tid >> 5;
    const int lane = tid & 31;
    const int nBase = blockIdx.x * 128;
    const int mBase = blockIdx.y * 128;

    const float* aSrc[4];
    const float* bSrc[4];
    int lRow[4], lQ[4];
    #pragma unroll
    for (int i = 0; i < 4; i++) {
        int slot = tid + i * 256;
        int r = slot >> 3;
        lRow[i] = r;
        lQ[i] = slot & 7;
        int m = mBase + r;
        int bidx = m >> 9, sidx = m & 511;
        aSrc[i] = (sidx == 0) ? (emb + (size_t)bidx * DD)
                              : (x + ((size_t)bidx * SS + (sidx - 1)) * DD);
        bSrc[i] = W_ih + (size_t)(nBase + r) * DD;
    }

    float acc[4][4][4];
    #pragma unroll
    for (int mf = 0; mf < 4; mf++)
        #pragma unroll
        for (int nf = 0; nf < 4; nf++)
            #pragma unroll
            for (int r = 0; r < 4; r++) acc[mf][nf][r] = 0.f;

    const int wm = (wid >> 2) * 64;
    const int wn = (wid & 3) * 32;
    const int lg = lane >> 2;
    const int lt = lane & 3;

    float4 pfA[4], pfB[4];
    #pragma unroll
    for (int i = 0; i < 4; i++) {
        pfA[i] = *(const float4*)(aSrc[i] + lQ[i] * 4);
        pfB[i] = *(const float4*)(bSrc[i] + lQ[i] * 4);
    }

    #pragma unroll 1
    for (int c = 0; c < DD / KC; c++) {
        #pragma unroll
        for (int i = 0; i < 4; i++) {
            uint32_t* pa = &As[lRow[i] * ASTR + lQ[i] * 4];
            uint32_t* pb = &Bs[lRow[i] * ASTR + lQ[i] * 4];
            pa[0] = to_tf32(pfA[i].x); pa[1] = to_tf32(pfA[i].y);
            pa[2] = to_tf32(pfA[i].z); pa[3] = to_tf32(pfA[i].w);
            pb[0] = to_tf32(pfB[i].x); pb[1] = to_tf32(pfB[i].y);
            pb[2] = to_tf32(pfB[i].z); pb[3] = to_tf32(pfB[i].w);
        }
        __syncthreads();

        if (c + 1 < DD / KC) {
            int ksrc = (c + 1) * KC;
            #pragma unroll
            for (int i = 0; i < 4; i++) {
                pfA[i] = *(const float4*)(aSrc[i] + ksrc + lQ[i] * 4);
                pfB[i] = *(const float4*)(bSrc[i] + ksrc + lQ[i] * 4);
            }
        }

        #pragma unroll
        for (int kk = 0; kk < KC; kk += 8) {
            uint32_t a[4][4];
            #pragma unroll
            for (int mf = 0; mf < 4; mf++) {
                int r = wm + mf * 16 + lg;
                a[mf][0] = As[r * ASTR + kk + lt];
                a[mf][1] = As[(r + 8) * ASTR + kk + lt];
                a[mf][2] = As[r * ASTR + kk + lt + 4];
                a[mf][3] = As[(r + 8) * ASTR + kk + lt + 4];
            }
            uint32_t b[4][2];
            #pragma unroll
            for (int nf = 0; nf < 4; nf++) {
                int n = wn + nf * 8 + lg;
                b[nf][0] = Bs[n * ASTR + kk + lt];
                b[nf][1] = Bs[n * ASTR + kk + lt + 4];
            }
            #pragma unroll
            for (int mf = 0; mf < 4; mf++)
                #pragma unroll
                for (int nf = 0; nf < 4; nf++)
                    mma_tf32(acc[mf][nf][0], acc[mf][nf][1], acc[mf][nf][2], acc[mf][nf][3],
                             a[mf][0], a[mf][1], a[mf][2], a[mf][3],
                             b[nf][0], b[nf][1]);
        }
        __syncthreads();
    }

    #pragma unroll
    for (int nf = 0; nf < 4; nf++) {
        int n0 = nBase + wn + nf * 8 + 2 * lt;
        float bias0 = b_ih[n0] + b_hh[n0];
        float bias1 = b_ih[n0 + 1] + b_hh[n0 + 1];
        #pragma unroll
        for (int mf = 0; mf < 4; mf++) {
            int m0 = mBase + wm + mf * 16 + lg;
            float2 v0, v1;
            v0.x = acc[mf][nf][0] + bias0;
            v0.y = acc[mf][nf][1] + bias1;
            v1.x = acc[mf][nf][2] + bias0;
            v1.y = acc[mf][nf][3] + bias1;
            *(float2*)(g_xg + (size_t)m0 * GG + n0) = v0;
            *(float2*)(g_xg + (size_t)(m0 + 8) * GG + n0) = v1;
        }
    }
}

// ---------------- kernel 2: persistent LSTM recurrence (tensor-core) ---------
// 128 blocks = 32 hidden-groups (16 units) x 4 batch-groups (16 batches).
// Per block: gates[16 batch, 64 rows] = h[16,512] @ Wslice^T[64,512].
// 8 warps = 8 K-slices of 64. W_hh tf32 fragments live in REGISTERS (128/thread)
// for the whole 512-step loop. Per step: stage h (tf32) -> mma -> smem reduce.
#define HS_STRIDE 516          // h smem row stride (words)
#define RED_NSTR 17            // red: [ksl][n(64)][m(17)]
#define RED_KSTR (64 * RED_NSTR)

__global__ __launch_bounds__(256, 1) void lstm_rec_kernel(
    const float* __restrict__ h_n, const float* __restrict__ c_n,
    const float* __restrict__ W_hh, float* __restrict__ out)
{
    extern __shared__ uint32_t sm[];
    uint32_t* hs = sm;                                // 16 x 516 (tf32 bits)
    float* red = (float*)(sm + 16 * HS_STRIDE);       // 8 x 1088

    const int tid = threadIdx.x;
    const int hg = blockIdx.x & 31;
    const int bg = blockIdx.x >> 5;
    const int j0 = hg * 16;
    const int b0 = bg * 16;

    const int wid  = tid >> 5;
    const int lane = tid & 31;
    const int lg = lane >> 2;
    const int lt = lane & 3;
    const int ksl = wid;          // K slice: [ksl*64, ksl*64+64)
    const int kbase = ksl * 64;

    // -------- load W_hh fragments into registers (once) ----------------------
    // local row nloc = gate*16 + jj ; global row = gate*HH + j0 + jj
    uint32_t Wf[8][8][2];
    #pragma unroll
    for (int nf = 0; nf < 8; nf++) {
        int nloc = nf * 8 + lg;
        int grow = (nloc >> 4) * HH + j0 + (nloc & 15);
        const float* wr = W_hh + (size_t)grow * HH + kbase + lt;
        #pragma unroll
        for (int kb = 0; kb < 8; kb++) {
            Wf[nf][kb][0] = to_tf32(wr[kb * 8]);
            Wf[nf][kb][1] = to_tf32(wr[kb * 8 + 4]);
        }
    }

    // activation mapping
    const int jj_a = tid & 15;
    const int bb_a = tid >> 4;
    float creg = c_n[(size_t)(b0 + bb_a) * HH + j0 + jj_a];

    #pragma unroll 1
    for (int t = 0; t < SS; t++) {
        if (t > 0) {
            if (tid == 0) {
                volatile unsigned int* p = &g_cnt[bg * SS + (t - 1)];
                while (*p < 32u) { }
                __threadfence();
            }
            __syncthreads();
        }

        // stage h_{t-1} (tf32-rounded) for our 16 batches
        for (int idx = tid; idx < 16 * 128; idx += 256) {
            int bb = idx >> 7;
            int kq = (idx & 127) * 4;
            float4 v;
            if (t == 0)
                v = *(const float4*)(h_n + (size_t)(b0 + bb) * HH + kq);
            else
                v = __ldcg((const float4*)(out + ((size_t)(b0 + bb) * SS + (t - 1)) * HH + kq));
            uint4 u;
            u.x = to_tf32(v.x); u.y = to_tf32(v.y);
            u.z = to_tf32(v.z); u.w = to_tf32(v.w);
            *(uint4*)(hs + bb * HS_STRIDE + kq) = u;
        }

        // xg loads issued early
        size_t xb = ((size_t)(b0 + bb_a) * SS + t) * GG + j0 + jj_a;
        float xg0 = g_xg[xb];
        float xg1 = g_xg[xb + HH];
        float xg2 = g_xg[xb + 2 * HH];
        float xg3 = g_xg[xb + 3 * HH];
        __syncthreads();

        // mma over this warp's K slice
        float acc[8][4];
        #pragma unroll
        for (int nf = 0; nf < 8; nf++)
            #pragma unroll
            for (int r = 0; r < 4; r++) acc[nf][r] = 0.f;

        #pragma unroll
        for (int kb = 0; kb < 8; kb++) {
            int k = kbase + kb * 8 + lt;
            uint32_t a0 = hs[lg * HS_STRIDE + k];
            uint32_t a1 = hs[(8 + lg) * HS_STRIDE + k];
            uint32_t a2 = hs[lg * HS_STRIDE + k + 4];
            uint32_t a3 = hs[(8 + lg) * HS_STRIDE + k + 4];
            #pragma unroll
            for (int nf = 0; nf < 8; nf++)
                mma_tf32(acc[nf][0], acc[nf][1], acc[nf][2], acc[nf][3],
                         a0, a1, a2, a3, Wf[nf][kb][0], Wf[nf][kb][1]);
        }

        // write partials: red[ksl][n][m]
        float* rbase = red + ksl * RED_KSTR;
        #pragma unroll
        for (int nf = 0; nf < 8; nf++) {
            int n0 = nf * 8 + 2 * lt;
            rbase[n0 * RED_NSTR + lg]           = acc[nf][0];
            rbase[(n0 + 1) * RED_NSTR + lg]     = acc[nf][1];
            rbase[n0 * RED_NSTR + 8 + lg]       = acc[nf][2];
            rbase[(n0 + 1) * RED_NSTR + 8 + lg] = acc[nf][3];
        }
        __syncthreads();

        // reduce 8 K-slices + LSTM elementwise for (jj_a, bb_a)
        float s0 = 0.f, s1 = 0.f, s2 = 0.f, s3 = 0.f;
        #pragma unroll
        for (int ks2 = 0; ks2 < 8; ks2++) {
            const float* rp = red + ks2 * RED_KSTR;
            s0 += rp[(0 * 16 + jj_a) * RED_NSTR + bb_a];
            s1 += rp[(1 * 16 + jj_a) * RED_NSTR + bb_a];
            s2 += rp[(2 * 16 + jj_a) * RED_NSTR + bb_a];
            s3 += rp[(3 * 16 + jj_a) * RED_NSTR + bb_a];
        }
        float ig = 1.f / (1.f + __expf(-(xg0 + s0)));
        float fg = 1.f / (1.f + __expf(-(xg1 + s1)));
        float gc = tanhf(xg2 + s2);
        float og = 1.f / (1.f + __expf(-(xg3 + s3)));
        creg = fg * creg + ig * gc;
        float hval = og * tanhf(creg);
        out[((size_t)(b0 + bb_a) * SS + t) * HH + j0 + jj_a] = hval;

        __syncthreads();
        if (tid == 0) {
            __threadfence();
            atomicAdd(&g_cnt[bg * SS + t], 1u);
        }
    }
}

// ---------------- launch ------------------------------------------------------
extern "C" void kernel_launch(void* const* d_in, const int* in_sizes, int n_in,
                              void* d_out, int out_size)
{
    const float* x    = (const float*)d_in[0];
    const float* emb  = (const float*)d_in[1];
    const float* h_n  = (const float*)d_in[2];
    const float* c_n  = (const float*)d_in[3];
    const float* W_ih = (const float*)d_in[4];
    const float* W_hh = (const float*)d_in[5];
    const float* b_ih = (const float*)d_in[6];
    const float* b_hh = (const float*)d_in[7];
    float* out = (float*)d_out;

    const int smemRec = (16 * HS_STRIDE + 8 * RED_KSTR) * (int)sizeof(float); // 67,840 B
    cudaFuncSetAttribute(lstm_rec_kernel, cudaFuncAttributeMaxDynamicSharedMemorySize, smemRec);

    zero_cnt_kernel<<<2, 1024>>>();
    xg_mma_kernel<<<dim3(GG / 128, (BB * SS) / 128), 256>>>(x, emb, W_ih, b_ih, b_hh);
    lstm_rec_kernel<<<NBLK, 256, smemRec>>>(h_n, c_n, W_hh, out);
}